// round 7
// baseline (speedup 1.0000x reference)
#include <cuda_runtime.h>
#include <cuda_fp16.h>
#include <cstdint>

// ---------------- problem constants ----------------
#define B_SZ   32768
#define DIN    512
#define DOUT   512
#define NLEV   10
#define NHB    64                  // histogram/scatter blocks (x512 thr)

// ---------------- GEMM tiling ----------------
#define BM     128
#define BN     256
#define BK     32                  // k per stage (fp16) = 64 B per row
#define NKB    (DIN / BK)          // 16 K-blocks
#define NSTG   4                   // cp.async pipeline depth
#define MAX_MT 266                 // sum ceil(count_l/128) <= 256 + 9
#define NT     (DOUT / BN)         // 2 N-tiles
#define A_STG  (BM * 64)           // 8192 B per stage
#define B_STG  (BN * 64)           // 16384 B per stage
#define STG_TOT (A_STG + B_STG)    // 24576 B
#define SMEM_BYTES (NSTG * STG_TOT)   // 98304

// ---------------- device scratch ----------------
__device__ int g_part[NHB][16];    // per-block histogram partials (plain stores)
__device__ int g_counts[NLEV];
__device__ int g_offsets[NLEV];
__device__ int g_rows[B_SZ];
// folded per-level matrices in fp16, [level][n][k]
__device__ __align__(16) __half g_M16[NLEV * DOUT * DIN];
// x pre-gathered into sorted order, fp16, [sorted_row][k]
__device__ __align__(16) __half g_X16[(size_t)B_SZ * DIN];

// ---------------- PTX helpers (all plain sm_80+/75+, no "a"-gated) --------
__device__ __forceinline__ uint32_t smem_u32(const void* p) {
    uint32_t a;
    asm("{ .reg .u64 t; cvta.to.shared.u64 t, %1; cvt.u32.u64 %0, t; }" : "=r"(a) : "l"(p));
    return a;
}
#define CP16(dst, src) \
    asm volatile("cp.async.cg.shared.global [%0], [%1], 16;" :: "r"(dst), "l"(src))
#define CP_COMMIT() asm volatile("cp.async.commit_group;" ::: "memory")
#define CP_WAIT2()  asm volatile("cp.async.wait_group 2;" ::: "memory")

#define LDSM4(r0, r1, r2, r3, addr) \
    asm volatile("ldmatrix.sync.aligned.m8n8.x4.shared.b16 {%0,%1,%2,%3}, [%4];" \
        : "=r"(r0), "=r"(r1), "=r"(r2), "=r"(r3) : "r"(addr))

__device__ __forceinline__ void mma16(float* d, const uint32_t* a, const uint32_t* b) {
    asm volatile(
        "mma.sync.aligned.m16n8k16.row.col.f32.f16.f16.f32 "
        "{%0,%1,%2,%3}, {%4,%5,%6,%7}, {%8,%9}, {%0,%1,%2,%3};"
        : "+f"(d[0]), "+f"(d[1]), "+f"(d[2]), "+f"(d[3])
        : "r"(a[0]), "r"(a[1]), "r"(a[2]), "r"(a[3]), "r"(b[0]), "r"(b[1]));
}

// swizzled byte offset of 16B unit u (0..3) within 64B row `row`
__device__ __forceinline__ uint32_t swz(int row, int u) {
    return (uint32_t)row * 64u + (uint32_t)((u ^ ((row >> 1) & 3)) << 4);
}

// per-block int64-vs-int32 detection: ballot over first 2KB (L2-hot).
__device__ __forceinline__ int detect_is64(const void* val, int tid) {
    int bad = 0;
    if (tid < 256) bad = (((const unsigned long long*)val)[tid] >= 10ULL);
    return __syncthreads_count(bad) == 0;
}
__device__ __forceinline__ int load_val(const void* val, int b, int is64) {
    int v = is64 ? (int)((const long long*)val)[b] : ((const int*)val)[b];
    return v < 0 ? 0 : (v > 9 ? 9 : v);
}

// =================================================================
// Kernel 1 (fused): blocks 0..63 = histogram partials,
//                   blocks 64..191 = fold M[v] = sum_l C[v,l]*W[l] (fp16)
// =================================================================
__global__ void k_prep(const void* __restrict__ val, const float* __restrict__ W,
                       const float* __restrict__ gates, const float* __restrict__ attn) {
    int tid = threadIdx.x, bid = blockIdx.x;
    if (bid < NHB) {
        __shared__ int sc[NLEV];
        int is64 = detect_is64(val, tid);          // includes a __syncthreads
        if (tid < NLEV) sc[tid] = 0;
        __syncthreads();
        int b = bid * 512 + tid;
        atomicAdd(&sc[load_val(val, b, is64)], 1);
        __syncthreads();
        if (tid < NLEV) g_part[bid][tid] = sc[tid];
    } else {
        __shared__ float sC[NLEV][NLEV];
        if (tid < NLEV) {
            int v = tid;
            float m = -1e30f;
            for (int l = 0; l < NLEV; l++) m = fmaxf(m, attn[v * NLEV + l]);
            float e[NLEV]; float ssum = 0.f;
            for (int l = 0; l < NLEV; l++) { e[l] = expf(attn[v * NLEV + l] - m); ssum += e[l]; }
            float inv = 1.f / ssum;
            float gv = 1.f / (1.f + expf(-gates[v]));
            for (int l = 0; l < NLEV; l++) {
                float gl = 1.f / (1.f + expf(-gates[l]));
                sC[v][l] = 0.3f * e[l] * inv * gl + ((l == v) ? 0.7f * gv : 0.f);
            }
        }
        __syncthreads();

        int p  = (bid - NHB) * 512 + tid;         // 0 .. 65535
        int n  = p >> 7;                          // output feature 0..511
        int k4 = p & 127;                         // float4 index along K

        float4 w[NLEV];
#pragma unroll
        for (int l = 0; l < NLEV; l++)
            w[l] = __ldg((const float4*)(W + ((size_t)l * DOUT + n) * DIN) + k4);

#pragma unroll
        for (int v = 0; v < NLEV; v++) {
            float4 a = make_float4(0.f, 0.f, 0.f, 0.f);
#pragma unroll
            for (int l = 0; l < NLEV; l++) {
                float cc = sC[v][l];
                a.x += cc * w[l].x; a.y += cc * w[l].y;
                a.z += cc * w[l].z; a.w += cc * w[l].w;
            }
            __half2 h0 = __floats2half2_rn(a.x, a.y);
            __half2 h1 = __floats2half2_rn(a.z, a.w);
            uint2 o;
            o.x = *reinterpret_cast<unsigned*>(&h0);
            o.y = *reinterpret_cast<unsigned*>(&h1);
            *(uint2*)(g_M16 + ((size_t)v * DOUT + n) * DIN + (size_t)k4 * 4) = o;
        }
    }
}

// =================================================================
// Kernel 2: fused scan + scatter + gather/convert x -> fp16 sorted.
// =================================================================
__global__ void k_scatter_xcvt(const void* __restrict__ val,
                               const float* __restrict__ x) {
    __shared__ int scnt[NLEV], sprev[NLEV], sbase[NLEV], srank[NLEV];
    __shared__ int sdst[512];
    int tid = threadIdx.x, bid = blockIdx.x;
    int is64 = detect_is64(val, tid);

    if (tid < NLEV) {
        int tot = 0, before = 0;
        for (int b = 0; b < NHB; b++) {
            int p = g_part[b][tid];
            if (b < bid) before += p;
            tot += p;
        }
        scnt[tid] = tot; sprev[tid] = before; srank[tid] = 0;
    }
    __syncthreads();
    if (tid == 0) {
        int a = 0;
        for (int l = 0; l < NLEV; l++) {
            sbase[l] = a + sprev[l];
            if (bid == 0) { g_counts[l] = scnt[l]; g_offsets[l] = a; }
            a += scnt[l];
        }
    }
    __syncthreads();

    int b = bid * 512 + tid;
    int v = load_val(val, b, is64);
    int rank = atomicAdd(&srank[v], 1);
    int dst = sbase[v] + rank;
    g_rows[dst] = b;
    sdst[tid] = dst;
    __syncthreads();

    // gather + fp16 convert: 4 rows in flight, 128 threads per row
    int grp = tid >> 7;        // 0..3
    int t   = tid & 127;       // float4 index within row
#pragma unroll 8
    for (int i = 0; i < 128; i++) {
        int r = i * 4 + grp;                       // local row 0..511
        int srcrow = bid * 512 + r;
        float4 vv = __ldg((const float4*)(x + (size_t)srcrow * DIN) + t);
        __half2 h0 = __floats2half2_rn(vv.x, vv.y);
        __half2 h1 = __floats2half2_rn(vv.z, vv.w);
        uint2 o;
        o.x = *reinterpret_cast<unsigned*>(&h0);
        o.y = *reinterpret_cast<unsigned*>(&h1);
        ((uint2*)(g_X16 + (size_t)sdst[r] * DIN))[t] = o;
    }
}

// =================================================================
// Kernel 3: fp16 GEMM  out[g_rows[r]] = M16[level] @ X16[r] + bias
//   CTA 128x256, 256 threads = 8 warps of 64x64, mma.m16n8k16,
//   ldmatrix fragments, 4-stage cp.async pipeline, 1 CTA/SM.
//   Producers: threads<128 fill A rows; ALL 256 threads fill B rows.
// =================================================================
__global__ void __launch_bounds__(256, 1) padic_gemm(
    const float* __restrict__ bias, float* __restrict__ out) {
    // ---- tile map ----
    int mt = blockIdx.x, ntile = blockIdx.y;
    int level = -1, tj = 0, acc = 0;
#pragma unroll
    for (int l = 0; l < NLEV; l++) {
        int c = g_counts[l];
        int tl = (c + BM - 1) >> 7;
        if (level < 0 && mt < acc + tl) { level = l; tj = mt - acc; }
        acc += tl;
    }
    if (level < 0) return;
    int base = g_offsets[level] + tj * BM;
    int cnt  = g_counts[level] - tj * BM;
    if (cnt > BM) cnt = BM;

    extern __shared__ char smem[];
    uint32_t sb = smem_u32(smem);
    int tid = threadIdx.x, lane = tid & 31, wid = tid >> 5;
    int wm = (wid & 1) * 64;          // warp M origin (2 down)
    int wn = (wid >> 1) * 64;         // warp N origin (4 across)

    // producers: A rows by threads<128, B rows by all 256 threads
    bool isA = tid < 128;
    int rowA = base + tid; if (rowA > B_SZ - 1) rowA = B_SZ - 1;
    const char* srcA = (const char*)(g_X16 + (size_t)rowA * DIN);
    const char* srcB = (const char*)(g_M16 + ((size_t)level * DOUT + (size_t)(ntile * BN + tid)) * DIN);
    uint32_t swzA[4], swzB[4];
#pragma unroll
    for (int u = 0; u < 4; u++) {
        swzA[u] = swz(tid & 127, u);
        swzB[u] = (uint32_t)A_STG + swz(tid, u);
    }

    float accum[4][8][4];
#pragma unroll
    for (int mf = 0; mf < 4; mf++)
#pragma unroll
        for (int nf = 0; nf < 8; nf++)
#pragma unroll
            for (int q = 0; q < 4; q++) accum[mf][nf][q] = 0.f;

    // ---- prologue: stages 0..2 ----
#pragma unroll
    for (int p = 0; p < NSTG - 1; p++) {
        uint32_t sa = sb + p * STG_TOT;
        if (isA) {
#pragma unroll
            for (int u = 0; u < 4; u++)
                CP16(sa + swzA[u], srcA + p * 64 + u * 16);
        }
#pragma unroll
        for (int u = 0; u < 4; u++)
            CP16(sa + swzB[u], srcB + p * 64 + u * 16);
        CP_COMMIT();
    }

    // precompute LDSM lane addresses (relative to stage base)
    int sub = lane >> 3, rr = lane & 7;
    int arow = wm + (sub & 1) * 8 + rr;
    int au   = sub >> 1;
    int brow = wn + (sub >> 1) * 8 + rr;
    int bu   = sub & 1;

    // ---- mainloop: wait(stage kb) ; barrier ; prefetch(kb+3) ; compute(kb) ----
    for (int kb = 0; kb < NKB; kb++) {
        CP_WAIT2();
        __syncthreads();

        if (kb + NSTG - 1 < NKB) {
            int p = kb + NSTG - 1;
            uint32_t sa = sb + (p & (NSTG - 1)) * STG_TOT;
            if (isA) {
#pragma unroll
                for (int u = 0; u < 4; u++)
                    CP16(sa + swzA[u], srcA + p * 64 + u * 16);
            }
#pragma unroll
            for (int u = 0; u < 4; u++)
                CP16(sa + swzB[u], srcB + p * 64 + u * 16);
        }
        CP_COMMIT();

        uint32_t Abase = sb + (kb & (NSTG - 1)) * STG_TOT;
        uint32_t Bbase = Abase + A_STG;

#pragma unroll
        for (int ks = 0; ks < 2; ks++) {
            uint32_t afr[4][4];
            uint32_t bfr[8][2];
#pragma unroll
            for (int mf = 0; mf < 4; mf++) {
                int rowm = arow + mf * 16;
                LDSM4(afr[mf][0], afr[mf][1], afr[mf][2], afr[mf][3],
                      Abase + swz(rowm, ks * 2 + au));
            }
#pragma unroll
            for (int bf = 0; bf < 4; bf++) {
                int rown = brow + bf * 16;
                LDSM4(bfr[bf * 2][0], bfr[bf * 2][1], bfr[bf * 2 + 1][0], bfr[bf * 2 + 1][1],
                      Bbase + swz(rown, ks * 2 + bu));
            }
#pragma unroll
            for (int mf = 0; mf < 4; mf++)
#pragma unroll
                for (int nf = 0; nf < 8; nf++)
                    mma16(accum[mf][nf], afr[mf], bfr[nf]);
        }
    }

    // ---- epilogue: add bias, scatter rows back ----
    int colbase = ntile * BN + wn;
    float2 bb[8];
#pragma unroll
    for (int nf = 0; nf < 8; nf++)
        bb[nf] = __ldg((const float2*)(bias + colbase + nf * 8 + (lane & 3) * 2));
#pragma unroll
    for (int mf = 0; mf < 4; mf++) {
        int row0 = wm + mf * 16 + (lane >> 2);
        int row1 = row0 + 8;
        int g0 = g_rows[base + (row0 < cnt ? row0 : 0)];
        int g1 = g_rows[base + (row1 < cnt ? row1 : 0)];
        float* o0 = out + (size_t)g0 * DOUT;
        float* o1 = out + (size_t)g1 * DOUT;
        bool v0 = row0 < cnt, v1 = row1 < cnt;
#pragma unroll
        for (int nf = 0; nf < 8; nf++) {
            int col = colbase + nf * 8 + (lane & 3) * 2;
            if (v0) {
                float2 w0;
                w0.x = accum[mf][nf][0] + bb[nf].x;
                w0.y = accum[mf][nf][1] + bb[nf].y;
                *(float2*)(o0 + col) = w0;
            }
            if (v1) {
                float2 w1;
                w1.x = accum[mf][nf][2] + bb[nf].x;
                w1.y = accum[mf][nf][3] + bb[nf].y;
                *(float2*)(o1 + col) = w1;
            }
        }
    }
}

// =================================================================
// kernel_launch
// =================================================================
extern "C" void kernel_launch(void* const* d_in, const int* in_sizes, int n_in,
                              void* d_out, int out_size) {
    const float* x     = (const float*)d_in[0];
    const void*  val   = d_in[1];
    const float* W     = (const float*)d_in[2];
    const float* gates = (const float*)d_in[3];
    const float* attn  = (const float*)d_in[4];
    const float* bias  = (const float*)d_in[5];
    float*       out   = (float*)d_out;

    cudaFuncSetAttribute(padic_gemm, cudaFuncAttributeMaxDynamicSharedMemorySize, SMEM_BYTES);

    k_prep<<<NHB + 128, 512>>>(val, W, gates, attn);
    k_scatter_xcvt<<<NHB, 512>>>(val, x);
    padic_gemm<<<dim3(MAX_MT, NT), 256, SMEM_BYTES>>>(bias, out);
}

// round 8
// speedup vs baseline: 1.1158x; 1.1158x over previous
#include <cuda_runtime.h>
#include <cuda_fp16.h>
#include <cstdint>

// ---------------- problem constants ----------------
#define B_SZ   32768
#define DIN    512
#define DOUT   512
#define NLEV   10
#define NHB    64                  // histogram/scatter blocks (x512 thr)

// ---------------- GEMM tiling ----------------
#define BM     128
#define BN     128
#define BK     64                  // k per stage (fp16) = 128 B per row
#define NKB    (DIN / BK)          // 8 K-blocks
#define NSTG   2                   // cp.async pipeline depth
#define MAX_MT 266                 // sum ceil(count_l/128) <= 256 + 9
#define NT     (DOUT / BN)         // 4 N-tiles
#define A_STG  (BM * 128)          // 16384 B per stage
#define STG_TOT (2 * A_STG)        // 32768 B (A + B)
#define SMEM_BYTES (NSTG * STG_TOT)   // 65536

// ---------------- device scratch ----------------
__device__ int g_part[NHB][16];    // per-block histogram partials (plain stores)
__device__ int g_counts[NLEV];
__device__ int g_offsets[NLEV];
__device__ int g_rows[B_SZ];
// folded per-level matrices in fp16, [level][n][k]
__device__ __align__(16) __half g_M16[NLEV * DOUT * DIN];
// x pre-gathered into sorted order, fp16, padded +BM rows for ragged tiles
__device__ __align__(16) __half g_X16[(size_t)(B_SZ + BM) * DIN];

// ---------------- PTX helpers (all plain sm_80+/75+, no "a"-gated) --------
__device__ __forceinline__ uint32_t smem_u32(const void* p) {
    uint32_t a;
    asm("{ .reg .u64 t; cvta.to.shared.u64 t, %1; cvt.u32.u64 %0, t; }" : "=r"(a) : "l"(p));
    return a;
}
#define CP16(dst, src) \
    asm volatile("cp.async.cg.shared.global [%0], [%1], 16;" :: "r"(dst), "l"(src))
#define CP_COMMIT() asm volatile("cp.async.commit_group;" ::: "memory")
#define CP_WAIT0()  asm volatile("cp.async.wait_group 0;" ::: "memory")

#define LDSM4(r0, r1, r2, r3, addr) \
    asm volatile("ldmatrix.sync.aligned.m8n8.x4.shared.b16 {%0,%1,%2,%3}, [%4];" \
        : "=r"(r0), "=r"(r1), "=r"(r2), "=r"(r3) : "r"(addr))

__device__ __forceinline__ void mma16(float* d, const uint32_t* a, const uint32_t* b) {
    asm volatile(
        "mma.sync.aligned.m16n8k16.row.col.f32.f16.f16.f32 "
        "{%0,%1,%2,%3}, {%4,%5,%6,%7}, {%8,%9}, {%0,%1,%2,%3};"
        : "+f"(d[0]), "+f"(d[1]), "+f"(d[2]), "+f"(d[3])
        : "r"(a[0]), "r"(a[1]), "r"(a[2]), "r"(a[3]), "r"(b[0]), "r"(b[1]));
}

// SW128 swizzle: byte offset of 16B unit u (0..7) within 128B row `row`
__device__ __forceinline__ uint32_t swz(int row, int u) {
    return (uint32_t)row * 128u + (uint32_t)((u ^ (row & 7)) << 4);
}

// per-block int64-vs-int32 detection: ballot over first 2KB (L2-hot).
__device__ __forceinline__ int detect_is64(const void* val, int tid) {
    int bad = 0;
    if (tid < 256) bad = (((const unsigned long long*)val)[tid] >= 10ULL);
    return __syncthreads_count(bad) == 0;
}
__device__ __forceinline__ int load_val(const void* val, int b, int is64) {
    int v = is64 ? (int)((const long long*)val)[b] : ((const int*)val)[b];
    return v < 0 ? 0 : (v > 9 ? 9 : v);
}

// =================================================================
// Kernel 1 (fused): blocks 0..63 = histogram partials,
//                   blocks 64..191 = fold M[v] = sum_l C[v,l]*W[l] (fp16)
// =================================================================
__global__ void k_prep(const void* __restrict__ val, const float* __restrict__ W,
                       const float* __restrict__ gates, const float* __restrict__ attn) {
    int tid = threadIdx.x, bid = blockIdx.x;
    if (bid < NHB) {
        __shared__ int sc[NLEV];
        int is64 = detect_is64(val, tid);          // includes a __syncthreads
        if (tid < NLEV) sc[tid] = 0;
        __syncthreads();
        int b = bid * 512 + tid;
        atomicAdd(&sc[load_val(val, b, is64)], 1);
        __syncthreads();
        if (tid < NLEV) g_part[bid][tid] = sc[tid];
    } else {
        __shared__ float sC[NLEV][NLEV];
        if (tid < NLEV) {
            int v = tid;
            float m = -1e30f;
            for (int l = 0; l < NLEV; l++) m = fmaxf(m, attn[v * NLEV + l]);
            float e[NLEV]; float ssum = 0.f;
            for (int l = 0; l < NLEV; l++) { e[l] = expf(attn[v * NLEV + l] - m); ssum += e[l]; }
            float inv = 1.f / ssum;
            float gv = 1.f / (1.f + expf(-gates[v]));
            for (int l = 0; l < NLEV; l++) {
                float gl = 1.f / (1.f + expf(-gates[l]));
                sC[v][l] = 0.3f * e[l] * inv * gl + ((l == v) ? 0.7f * gv : 0.f);
            }
        }
        __syncthreads();

        int p  = (bid - NHB) * 512 + tid;         // 0 .. 65535
        int n  = p >> 7;                          // output feature 0..511
        int k4 = p & 127;                         // float4 index along K

        float4 w[NLEV];
#pragma unroll
        for (int l = 0; l < NLEV; l++)
            w[l] = __ldg((const float4*)(W + ((size_t)l * DOUT + n) * DIN) + k4);

#pragma unroll
        for (int v = 0; v < NLEV; v++) {
            float4 a = make_float4(0.f, 0.f, 0.f, 0.f);
#pragma unroll
            for (int l = 0; l < NLEV; l++) {
                float cc = sC[v][l];
                a.x += cc * w[l].x; a.y += cc * w[l].y;
                a.z += cc * w[l].z; a.w += cc * w[l].w;
            }
            __half2 h0 = __floats2half2_rn(a.x, a.y);
            __half2 h1 = __floats2half2_rn(a.z, a.w);
            uint2 o;
            o.x = *reinterpret_cast<unsigned*>(&h0);
            o.y = *reinterpret_cast<unsigned*>(&h1);
            *(uint2*)(g_M16 + ((size_t)v * DOUT + n) * DIN + (size_t)k4 * 4) = o;
        }
    }
}

// =================================================================
// Kernel 2: fused scan + scatter + gather/convert x -> fp16 sorted.
// =================================================================
__global__ void k_scatter_xcvt(const void* __restrict__ val,
                               const float* __restrict__ x) {
    __shared__ int scnt[NLEV], sprev[NLEV], sbase[NLEV], srank[NLEV];
    __shared__ int sdst[512];
    int tid = threadIdx.x, bid = blockIdx.x;
    int is64 = detect_is64(val, tid);

    if (tid < NLEV) {
        int tot = 0, before = 0;
        for (int b = 0; b < NHB; b++) {
            int p = g_part[b][tid];
            if (b < bid) before += p;
            tot += p;
        }
        scnt[tid] = tot; sprev[tid] = before; srank[tid] = 0;
    }
    __syncthreads();
    if (tid == 0) {
        int a = 0;
        for (int l = 0; l < NLEV; l++) {
            sbase[l] = a + sprev[l];
            if (bid == 0) { g_counts[l] = scnt[l]; g_offsets[l] = a; }
            a += scnt[l];
        }
    }
    __syncthreads();

    int b = bid * 512 + tid;
    int v = load_val(val, b, is64);
    int rank = atomicAdd(&srank[v], 1);
    int dst = sbase[v] + rank;
    g_rows[dst] = b;
    sdst[tid] = dst;
    __syncthreads();

    // gather + fp16 convert: 4 rows in flight, 128 threads per row
    int grp = tid >> 7;        // 0..3
    int t   = tid & 127;       // float4 index within row
#pragma unroll 8
    for (int i = 0; i < 128; i++) {
        int r = i * 4 + grp;                       // local row 0..511
        int srcrow = bid * 512 + r;
        float4 vv = __ldg((const float4*)(x + (size_t)srcrow * DIN) + t);
        __half2 h0 = __floats2half2_rn(vv.x, vv.y);
        __half2 h1 = __floats2half2_rn(vv.z, vv.w);
        uint2 o;
        o.x = *reinterpret_cast<unsigned*>(&h0);
        o.y = *reinterpret_cast<unsigned*>(&h1);
        ((uint2*)(g_X16 + (size_t)sdst[r] * DIN))[t] = o;
    }
}

// =================================================================
// Kernel 3: fp16 GEMM  out[g_rows[r]] = M16[level] @ X16[r] + bias
//   CTA 128x128, 256 threads = 8 warps of 32x64, mma.m16n8k16,
//   BK=64, SW128 swizzle, COALESCED cp.async (4 full 128B lines per
//   warp-instr), 2-stage pipeline, 2 CTAs/SM.
// =================================================================
__global__ void __launch_bounds__(256, 2) padic_gemm(
    const float* __restrict__ bias, float* __restrict__ out) {
    // ---- tile map ----
    int mt = blockIdx.x, ntile = blockIdx.y;
    int level = -1, tj = 0, acc = 0;
#pragma unroll
    for (int l = 0; l < NLEV; l++) {
        int c = g_counts[l];
        int tl = (c + BM - 1) >> 7;
        if (level < 0 && mt < acc + tl) { level = l; tj = mt - acc; }
        acc += tl;
    }
    if (level < 0) return;
    int base = g_offsets[level] + tj * BM;
    int cnt  = g_counts[level] - tj * BM;
    if (cnt > BM) cnt = BM;

    extern __shared__ char smem[];
    uint32_t sb = smem_u32(smem);
    int tid = threadIdx.x, lane = tid & 31, wid = tid >> 5;
    int wm = (wid & 3) * 32;          // warp M origin (4 warps down)
    int wn = (wid >> 2) * 64;         // warp N origin (2 warps across)

    // producer mapping: thread t -> unit u = t&7 (16B within 128B chunk),
    // base row rb = t>>3 (0..31); sweeps add +32 rows.
    // Warp covers 4 consecutive rows' FULL 128B chunks -> 4 lines/instr.
    int u  = tid & 7;
    int rb = tid >> 3;
    const char* gA = (const char*)(g_X16 + (size_t)(base + rb) * DIN) + u * 16;
    const char* gB = (const char*)(g_M16 + ((size_t)level * DOUT
                     + (size_t)(ntile * BN + rb)) * DIN) + u * 16;
    uint32_t sA = (uint32_t)rb * 128u + (uint32_t)((u ^ (rb & 7)) << 4);
    uint32_t sB = sA + A_STG;

    float accum[2][8][4];
#pragma unroll
    for (int mf = 0; mf < 2; mf++)
#pragma unroll
        for (int nf = 0; nf < 8; nf++)
#pragma unroll
            for (int q = 0; q < 4; q++) accum[mf][nf][q] = 0.f;

    // ---- prologue: stage for kb=0 ----
    {
        uint32_t st = sb;
#pragma unroll
        for (int s = 0; s < 4; s++) {
            CP16(st + sA + s * 4096, gA + (size_t)s * 32 * 1024);
            CP16(st + sB + s * 4096, gB + (size_t)s * 32 * 1024);
        }
        CP_COMMIT();
    }

    // consumer LDSM lane mapping
    int sub = lane >> 3, rr = lane & 7;
    int arow = wm + (sub & 1) * 8 + rr;
    int au   = sub >> 1;
    int brow = wn + (sub >> 1) * 8 + rr;
    int bu   = sub & 1;

    // ---- mainloop: wait(kb) ; barrier ; prefetch(kb+1) ; compute(kb) ----
    for (int kb = 0; kb < NKB; kb++) {
        CP_WAIT0();
        __syncthreads();

        if (kb + 1 < NKB) {
            uint32_t st = sb + ((kb + 1) & 1) * STG_TOT;
            const char* ga = gA + (kb + 1) * 128;
            const char* gb = gB + (kb + 1) * 128;
#pragma unroll
            for (int s = 0; s < 4; s++) {
                CP16(st + sA + s * 4096, ga + (size_t)s * 32 * 1024);
                CP16(st + sB + s * 4096, gb + (size_t)s * 32 * 1024);
            }
        }
        CP_COMMIT();

        uint32_t Abase = sb + (kb & 1) * STG_TOT;
        uint32_t Bbase = Abase + A_STG;

#pragma unroll
        for (int ks = 0; ks < 4; ks++) {
            uint32_t afr[2][4];
            uint32_t bfr[8][2];
#pragma unroll
            for (int mf = 0; mf < 2; mf++) {
                int rowm = arow + mf * 16;
                LDSM4(afr[mf][0], afr[mf][1], afr[mf][2], afr[mf][3],
                      Abase + swz(rowm, ks * 2 + au));
            }
#pragma unroll
            for (int bf = 0; bf < 4; bf++) {
                int rown = brow + bf * 16;
                LDSM4(bfr[bf * 2][0], bfr[bf * 2][1], bfr[bf * 2 + 1][0], bfr[bf * 2 + 1][1],
                      Bbase + swz(rown, ks * 2 + bu));
            }
#pragma unroll
            for (int mf = 0; mf < 2; mf++)
#pragma unroll
                for (int nf = 0; nf < 8; nf++)
                    mma16(accum[mf][nf], afr[mf], bfr[nf]);
        }
    }

    // ---- epilogue: add bias, scatter rows back ----
    int colbase = ntile * BN + wn;
    float2 bb[8];
#pragma unroll
    for (int nf = 0; nf < 8; nf++)
        bb[nf] = __ldg((const float2*)(bias + colbase + nf * 8 + (lane & 3) * 2));
#pragma unroll
    for (int mf = 0; mf < 2; mf++) {
        int row0 = wm + mf * 16 + (lane >> 2);
        int row1 = row0 + 8;
        int g0 = g_rows[base + (row0 < cnt ? row0 : 0)];
        int g1 = g_rows[base + (row1 < cnt ? row1 : 0)];
        float* o0 = out + (size_t)g0 * DOUT;
        float* o1 = out + (size_t)g1 * DOUT;
        bool v0 = row0 < cnt, v1 = row1 < cnt;
#pragma unroll
        for (int nf = 0; nf < 8; nf++) {
            int col = colbase + nf * 8 + (lane & 3) * 2;
            if (v0) {
                float2 w0;
                w0.x = accum[mf][nf][0] + bb[nf].x;
                w0.y = accum[mf][nf][1] + bb[nf].y;
                *(float2*)(o0 + col) = w0;
            }
            if (v1) {
                float2 w1;
                w1.x = accum[mf][nf][2] + bb[nf].x;
                w1.y = accum[mf][nf][3] + bb[nf].y;
                *(float2*)(o1 + col) = w1;
            }
        }
    }
}

// =================================================================
// kernel_launch
// =================================================================
extern "C" void kernel_launch(void* const* d_in, const int* in_sizes, int n_in,
                              void* d_out, int out_size) {
    const float* x     = (const float*)d_in[0];
    const void*  val   = d_in[1];
    const float* W     = (const float*)d_in[2];
    const float* gates = (const float*)d_in[3];
    const float* attn  = (const float*)d_in[4];
    const float* bias  = (const float*)d_in[5];
    float*       out   = (float*)d_out;

    cudaFuncSetAttribute(padic_gemm, cudaFuncAttributeMaxDynamicSharedMemorySize, SMEM_BYTES);

    k_prep<<<NHB + 128, 512>>>(val, W, gates, attn);
    k_scatter_xcvt<<<NHB, 512>>>(val, x);
    padic_gemm<<<dim3(MAX_MT, NT), 256, SMEM_BYTES>>>(bias, out);
}

// round 9
// speedup vs baseline: 1.9616x; 1.7581x over previous
#include <cuda_runtime.h>
#include <cuda_fp16.h>
#include <cstdint>

// ---------------- problem constants ----------------
#define B_SZ   32768
#define DIN    512
#define DOUT   512
#define NLEV   10
#define NHB    64                  // histogram/scatter blocks (x512 thr)

// ---------------- GEMM tiling ----------------
#define BM     128
#define BN     128
#define BK     64                  // k per stage: A fp32 256B/row, B fp16 128B/row
#define NKB    (DIN / BK)          // 8 K-blocks
#define MAX_MT 266
#define NT     (DOUT / BN)         // 4 N-tiles
#define A_SZ   (BM * 256)          // 32768 B per stage (fp32)
#define B_SZ_S (BN * 128)          // 16384 B per stage (fp16)
#define STG_TOT (A_SZ + B_SZ_S)    // 49152 B
#define SMEM_BYTES (2 * STG_TOT)   // 98304

// ---------------- device scratch ----------------
__device__ int g_part[NHB][16];
__device__ int g_counts[NLEV];
__device__ int g_offsets[NLEV];
__device__ int g_rows[B_SZ];
// folded per-level matrices in fp16, [level][n][k]
__device__ __align__(16) __half g_M16[NLEV * DOUT * DIN];

// ---------------- PTX helpers ----------------
__device__ __forceinline__ uint32_t smem_u32(const void* p) {
    uint32_t a;
    asm("{ .reg .u64 t; cvta.to.shared.u64 t, %1; cvt.u32.u64 %0, t; }" : "=r"(a) : "l"(p));
    return a;
}
#define CP16(dst, src) \
    asm volatile("cp.async.cg.shared.global [%0], [%1], 16;" :: "r"(dst), "l"(src))
#define CP_COMMIT() asm volatile("cp.async.commit_group;" ::: "memory")
#define CP_WAIT0()  asm volatile("cp.async.wait_group 0;" ::: "memory")

#define LDSM4(r0, r1, r2, r3, addr) \
    asm volatile("ldmatrix.sync.aligned.m8n8.x4.shared.b16 {%0,%1,%2,%3}, [%4];" \
        : "=r"(r0), "=r"(r1), "=r"(r2), "=r"(r3) : "r"(addr))

__device__ __forceinline__ void mma16(float* d, const uint32_t* a, const uint32_t* b) {
    asm volatile(
        "mma.sync.aligned.m16n8k16.row.col.f32.f16.f16.f32 "
        "{%0,%1,%2,%3}, {%4,%5,%6,%7}, {%8,%9}, {%0,%1,%2,%3};"
        : "+f"(d[0]), "+f"(d[1]), "+f"(d[2]), "+f"(d[3])
        : "r"(a[0]), "r"(a[1]), "r"(a[2]), "r"(a[3]), "r"(b[0]), "r"(b[1]));
}

__device__ __forceinline__ uint32_t cvt2(float2 f) {
    __half2 h = __floats2half2_rn(f.x, f.y);
    return *reinterpret_cast<uint32_t*>(&h);
}

// B smem swizzle (128B rows, 8 x 16B units)
__device__ __forceinline__ uint32_t swzB(int row, int u) {
    return (uint32_t)row * 128u + (uint32_t)((u ^ (row & 7)) << 4);
}

// per-block int64-vs-int32 detection over first 2KB
__device__ __forceinline__ int detect_is64(const void* val, int tid) {
    int bad = 0;
    if (tid < 256) bad = (((const unsigned long long*)val)[tid] >= 10ULL);
    return __syncthreads_count(bad) == 0;
}
__device__ __forceinline__ int load_val(const void* val, int b, int is64) {
    int v = is64 ? (int)((const long long*)val)[b] : ((const int*)val)[b];
    return v < 0 ? 0 : (v > 9 ? 9 : v);
}

// =================================================================
// Kernel 1: per-block histogram partials
// =================================================================
__global__ void k_hist(const void* __restrict__ val) {
    __shared__ int sc[NLEV];
    int tid = threadIdx.x, bid = blockIdx.x;
    int is64 = detect_is64(val, tid);
    if (tid < NLEV) sc[tid] = 0;
    __syncthreads();
    atomicAdd(&sc[load_val(val, bid * 512 + tid, is64)], 1);
    __syncthreads();
    if (tid < NLEV) g_part[bid][tid] = sc[tid];
}

// =================================================================
// Kernel 2 (fused): blocks 0..63 = scan+scatter (g_rows only),
//                   blocks 64..191 = fold M[v] (fp16)
// =================================================================
__global__ void k_fused(const void* __restrict__ val, const float* __restrict__ W,
                        const float* __restrict__ gates, const float* __restrict__ attn) {
    int tid = threadIdx.x, bid = blockIdx.x;
    if (bid < NHB) {
        __shared__ int scnt[NLEV], sprev[NLEV], sbase[NLEV], srank[NLEV];
        int is64 = detect_is64(val, tid);
        if (tid < NLEV) {
            int tot = 0, before = 0;
            for (int b = 0; b < NHB; b++) {
                int p = g_part[b][tid];
                if (b < bid) before += p;
                tot += p;
            }
            scnt[tid] = tot; sprev[tid] = before; srank[tid] = 0;
        }
        __syncthreads();
        if (tid == 0) {
            int a = 0;
            for (int l = 0; l < NLEV; l++) {
                sbase[l] = a + sprev[l];
                if (bid == 0) { g_counts[l] = scnt[l]; g_offsets[l] = a; }
                a += scnt[l];
            }
        }
        __syncthreads();
        int b = bid * 512 + tid;
        int v = load_val(val, b, is64);
        int rank = atomicAdd(&srank[v], 1);
        g_rows[sbase[v] + rank] = b;
    } else {
        __shared__ float sC[NLEV][NLEV];
        if (tid < NLEV) {
            int v = tid;
            float m = -1e30f;
            for (int l = 0; l < NLEV; l++) m = fmaxf(m, attn[v * NLEV + l]);
            float e[NLEV]; float ssum = 0.f;
            for (int l = 0; l < NLEV; l++) { e[l] = expf(attn[v * NLEV + l] - m); ssum += e[l]; }
            float inv = 1.f / ssum;
            float gv = 1.f / (1.f + expf(-gates[v]));
            for (int l = 0; l < NLEV; l++) {
                float gl = 1.f / (1.f + expf(-gates[l]));
                sC[v][l] = 0.3f * e[l] * inv * gl + ((l == v) ? 0.7f * gv : 0.f);
            }
        }
        __syncthreads();

        int p  = (bid - NHB) * 512 + tid;
        int n  = p >> 7;
        int k4 = p & 127;

        float4 w[NLEV];
#pragma unroll
        for (int l = 0; l < NLEV; l++)
            w[l] = __ldg((const float4*)(W + ((size_t)l * DOUT + n) * DIN) + k4);

#pragma unroll
        for (int v = 0; v < NLEV; v++) {
            float4 a = make_float4(0.f, 0.f, 0.f, 0.f);
#pragma unroll
            for (int l = 0; l < NLEV; l++) {
                float cc = sC[v][l];
                a.x += cc * w[l].x; a.y += cc * w[l].y;
                a.z += cc * w[l].z; a.w += cc * w[l].w;
            }
            __half2 h0 = __floats2half2_rn(a.x, a.y);
            __half2 h1 = __floats2half2_rn(a.z, a.w);
            uint2 o;
            o.x = *reinterpret_cast<unsigned*>(&h0);
            o.y = *reinterpret_cast<unsigned*>(&h1);
            *(uint2*)(g_M16 + ((size_t)v * DOUT + n) * DIN + (size_t)k4 * 4) = o;
        }
    }
}

// =================================================================
// Kernel 3: GEMM  out[srow[r]] = M16[level] @ x[srow[r]] + bias
//   A = fp32 x rows gathered directly (cp.async 256B rows), converted
//   to fp16 in registers at fragment load (LDS.64 + cvt).
//   B = fp16 g_M16 via ldmatrix as before. 8 warps of 32x64.
// =================================================================
__global__ void __launch_bounds__(256, 2) padic_gemm(
    const float* __restrict__ x, const float* __restrict__ bias,
    float* __restrict__ out) {
    // ---- tile map ----
    int mt = blockIdx.x, ntile = blockIdx.y;
    int level = -1, tj = 0, acc = 0;
#pragma unroll
    for (int l = 0; l < NLEV; l++) {
        int c = g_counts[l];
        int tl = (c + BM - 1) >> 7;
        if (level < 0 && mt < acc + tl) { level = l; tj = mt - acc; }
        acc += tl;
    }
    if (level < 0) return;
    int base = g_offsets[level] + tj * BM;
    int cnt  = g_counts[level] - tj * BM;
    if (cnt > BM) cnt = BM;

    extern __shared__ char smem[];
    __shared__ int srow[BM];
    uint32_t sb = smem_u32(smem);
    int tid = threadIdx.x, lane = tid & 31, wid = tid >> 5;
    int wm = (wid & 3) * 32;
    int wn = (wid >> 2) * 64;

    // cache gathered row ids
    if (tid < BM) srow[tid] = g_rows[base + (tid < cnt ? tid : 0)];
    __syncthreads();

    // ---- producers ----
    // A: thread t -> row (t>>4)+16s (s=0..7), 16B unit u=t&15 of 256B chunk
    int uA = tid & 15, rA0 = tid >> 4;
    const char* pA[8];
#pragma unroll
    for (int s = 0; s < 8; s++)
        pA[s] = (const char*)(x + (size_t)srow[rA0 + 16 * s] * DIN) + uA * 16;
    uint32_t sA0 = (uint32_t)rA0 * 256u + (uint32_t)((uA ^ ((rA0 & 7) << 1)) << 4);
    // B: thread t -> row (t>>3)+32s (s=0..3), unit u=t&7 of 128B chunk
    int uB = tid & 7, rB0 = tid >> 3;
    const char* pB = (const char*)(g_M16 + ((size_t)level * DOUT
                     + (size_t)(ntile * BN + rB0)) * DIN) + uB * 16;
    uint32_t sB0 = (uint32_t)A_SZ + (uint32_t)rB0 * 128u
                 + (uint32_t)((uB ^ (rB0 & 7)) << 4);

    float accum[2][8][4];
#pragma unroll
    for (int mf = 0; mf < 2; mf++)
#pragma unroll
        for (int nf = 0; nf < 8; nf++)
#pragma unroll
            for (int q = 0; q < 4; q++) accum[mf][nf][q] = 0.f;

    // ---- prologue: stage 0 ----
    {
#pragma unroll
        for (int s = 0; s < 8; s++)
            CP16(sb + sA0 + s * 4096, pA[s]);
#pragma unroll
        for (int s = 0; s < 4; s++)
            CP16(sb + sB0 + s * 4096, pB + (size_t)s * 32768);
        CP_COMMIT();
    }

    // consumer lane constants
    int sub = lane >> 3, rr = lane & 7;
    int brow = wn + (sub >> 1) * 8 + rr;
    int bu   = sub & 1;
    int xorv = (lane >> 2) << 1;          // A swizzle xor for this lane's rows
    int inb  = (lane & 1) << 3;           // byte-in-unit
    int au0  = (lane & 3) >> 1;           // unit within k-group
    uint32_t abase0 = (uint32_t)(wm + (lane >> 2)) * 256u;

    // ---- mainloop ----
    for (int kb = 0; kb < NKB; kb++) {
        CP_WAIT0();
        __syncthreads();

        if (kb + 1 < NKB) {
            uint32_t st = sb + ((kb + 1) & 1) * STG_TOT;
#pragma unroll
            for (int s = 0; s < 8; s++)
                CP16(st + sA0 + s * 4096, pA[s] + (kb + 1) * 256);
#pragma unroll
            for (int s = 0; s < 4; s++)
                CP16(st + sB0 + s * 4096, pB + (kb + 1) * 128 + (size_t)s * 32768);
        }
        CP_COMMIT();

        uint32_t stg = (uint32_t)((kb & 1) * STG_TOT);
        const char* As = smem + stg;
        uint32_t Bb = sb + stg + A_SZ;

#pragma unroll
        for (int g = 0; g < 4; g++) {
            int u0 = 4 * g + au0;
            uint32_t col0 = (uint32_t)(((u0      ^ xorv) << 4) + inb);
            uint32_t col2 = (uint32_t)((((u0 + 2) ^ xorv) << 4) + inb);
            uint32_t afr[2][4];
            uint32_t bfr[8][2];
#pragma unroll
            for (int mf = 0; mf < 2; mf++) {
                uint32_t rb = abase0 + (uint32_t)mf * 4096u;
                afr[mf][0] = cvt2(*(const float2*)(As + rb + col0));
                afr[mf][1] = cvt2(*(const float2*)(As + rb + 2048 + col0));
                afr[mf][2] = cvt2(*(const float2*)(As + rb + col2));
                afr[mf][3] = cvt2(*(const float2*)(As + rb + 2048 + col2));
            }
#pragma unroll
            for (int bf = 0; bf < 4; bf++) {
                int rown = brow + bf * 16;
                LDSM4(bfr[bf * 2][0], bfr[bf * 2][1], bfr[bf * 2 + 1][0], bfr[bf * 2 + 1][1],
                      Bb + swzB(rown, g * 2 + bu));
            }
#pragma unroll
            for (int mf = 0; mf < 2; mf++)
#pragma unroll
                for (int nf = 0; nf < 8; nf++)
                    mma16(accum[mf][nf], afr[mf], bfr[nf]);
        }
    }

    // ---- epilogue ----
    int colbase = ntile * BN + wn;
    float2 bb[8];
#pragma unroll
    for (int nf = 0; nf < 8; nf++)
        bb[nf] = __ldg((const float2*)(bias + colbase + nf * 8 + (lane & 3) * 2));
#pragma unroll
    for (int mf = 0; mf < 2; mf++) {
        int row0 = wm + mf * 16 + (lane >> 2);
        int row1 = row0 + 8;
        float* o0 = out + (size_t)srow[row0] * DOUT;
        float* o1 = out + (size_t)srow[row1] * DOUT;
        bool v0 = row0 < cnt, v1 = row1 < cnt;
#pragma unroll
        for (int nf = 0; nf < 8; nf++) {
            int col = colbase + nf * 8 + (lane & 3) * 2;
            if (v0) {
                float2 w0;
                w0.x = accum[mf][nf][0] + bb[nf].x;
                w0.y = accum[mf][nf][1] + bb[nf].y;
                *(float2*)(o0 + col) = w0;
            }
            if (v1) {
                float2 w1;
                w1.x = accum[mf][nf][2] + bb[nf].x;
                w1.y = accum[mf][nf][3] + bb[nf].y;
                *(float2*)(o1 + col) = w1;
            }
        }
    }
}

// =================================================================
// kernel_launch
// =================================================================
extern "C" void kernel_launch(void* const* d_in, const int* in_sizes, int n_in,
                              void* d_out, int out_size) {
    const float* x     = (const float*)d_in[0];
    const void*  val   = d_in[1];
    const float* W     = (const float*)d_in[2];
    const float* gates = (const float*)d_in[3];
    const float* attn  = (const float*)d_in[4];
    const float* bias  = (const float*)d_in[5];
    float*       out   = (float*)d_out;

    cudaFuncSetAttribute(padic_gemm, cudaFuncAttributeMaxDynamicSharedMemorySize, SMEM_BYTES);

    k_hist<<<NHB, 512>>>(val);
    k_fused<<<NHB + 128, 512>>>(val, W, gates, attn);
    padic_gemm<<<dim3(MAX_MT, NT), 256, SMEM_BYTES>>>(x, bias, out);
}